// round 15
// baseline (speedup 1.0000x reference)
#include <cuda_runtime.h>
#include <cuda_fp16.h>
#include <cstdint>

#define N_NODES 50000
#define N_EDGES 800000
#define DIM_IN  128
#define DIM_HID 256
#define DIM_OUT 128

// ---------------- scratch (no allocations allowed) ----------------
__device__ __align__(16) float g_bufA[N_NODES * DIM_HID];   // 51.2 MB
__device__ __align__(16) float g_bufB[N_NODES * DIM_HID];   // 51.2 MB
__device__ __align__(16) uint16_t g_wt0[DIM_IN  * DIM_HID];
__device__ __align__(16) uint16_t g_wt1[DIM_HID * DIM_HID];
__device__ __align__(16) uint16_t g_wt2[DIM_HID * DIM_OUT];
__device__ unsigned long long g_degcnt[N_NODES];   // count<<40 | deg_fixed(2^-24)
__device__ float g_dinv[N_NODES];
__device__ int   g_count[N_NODES];
__device__ int   g_indptr[N_NODES];
__device__ int   g_cursor[N_NODES];
__device__ int   g_esrc[N_EDGES];
__device__ float g_enorm[N_EDGES];
__device__ int   g_i64;

__device__ __forceinline__ int clampi(int v) {
    return min(max(v, 0), N_NODES - 1);
}
__device__ __forceinline__ int eidx(const void* ei, int j, int e) {
    if (g_i64) return clampi((int)((const long long*)ei)[j * N_EDGES + e]);
    return clampi(((const int*)ei)[j * N_EDGES + e]);
}

// bf16 helpers
__device__ __forceinline__ float bflo(uint32_t u) { return __uint_as_float(u << 16); }
__device__ __forceinline__ float bfhi(uint32_t u) { return __uint_as_float(u & 0xffff0000u); }
__device__ __forceinline__ uint32_t bfpack(float lo, float hi) {
    uint32_t r;
    asm("cvt.rn.bf16x2.f32 %0, %1, %2;" : "=r"(r) : "f"(hi), "f"(lo));
    return r;
}
__device__ __forceinline__ uint16_t bf1(float f) {
    uint16_t r;
    asm("cvt.rn.bf16.f32 %0, %1;" : "=h"(r) : "f"(f));
    return r;
}
__device__ __forceinline__ uint32_t hfpack(float lo, float hi) {
    uint32_t r;
    asm("cvt.rn.f16x2.f32 %0, %1, %2;" : "=r"(r) : "f"(hi), "f"(lo));
    return r;
}
__device__ __forceinline__ void mma_bf16(float* c, const uint32_t* a, const uint32_t* b) {
    asm volatile(
        "mma.sync.aligned.m16n8k16.row.col.f32.bf16.bf16.f32 "
        "{%0,%1,%2,%3}, {%4,%5,%6,%7}, {%8,%9}, {%0,%1,%2,%3};"
        : "+f"(c[0]), "+f"(c[1]), "+f"(c[2]), "+f"(c[3])
        : "r"(a[0]), "r"(a[1]), "r"(a[2]), "r"(a[3]), "r"(b[0]), "r"(b[1]));
}
// cp.async helpers (sm_80 baseline PTX)
__device__ __forceinline__ uint32_t smem_u32(const void* p) {
    uint32_t a;
    asm("{ .reg .u64 t; cvta.to.shared.u64 t, %1; cvt.u32.u64 %0, t; }"
        : "=r"(a) : "l"(p));
    return a;
}
__device__ __forceinline__ void cpa16(uint32_t saddr, const void* g, int srcbytes) {
    asm volatile("cp.async.cg.shared.global [%0], [%1], 16, %2;"
                 :: "r"(saddr), "l"(g), "r"(srcbytes));
}
#define CP_COMMIT() asm volatile("cp.async.commit_group;" ::: "memory")
#define CP_WAIT(N)  asm volatile("cp.async.wait_group %0;" :: "n"(N) : "memory")

// ---------------- fused: dtype detect (block 0) + init + x->bf16 ----------------
#define NB_INIT 196                       // ceil(50000/256)
#define NB_CVT  12500                     // 50000*64/256 words
__global__ void k_pre(const int* __restrict__ ei32,
                      const float* __restrict__ x, uint32_t* __restrict__ xb) {
    int bid = blockIdx.x;
    if (bid == 0) {
        __shared__ int s_nz;
        if (threadIdx.x == 0) s_nz = 0;
        __syncthreads();
        int nz = 0;
        for (int t = threadIdx.x; t < 2048; t += blockDim.x)
            if (ei32[2 * t + 1] != 0) nz = 1;
        if (nz) atomicOr(&s_nz, 1);
        __syncthreads();
        if (threadIdx.x == 0) g_i64 = (s_nz == 0) ? 1 : 0;
    }
    if (bid < NB_INIT) {
        int i = bid * 256 + threadIdx.x;
        if (i < N_NODES) g_degcnt[i] = 0ull;
    } else {
        int i = (bid - NB_INIT) * 256 + threadIdx.x;
        if (i < N_NODES * (DIM_IN / 2)) {
            float2 v = ((const float2*)x)[i];
            xb[i] = bfpack(v.x, v.y);
        }
    }
}

// ---------------- graph build: packed degree+count, single atomic/edge ----------
__global__ void k_degcount(const void* __restrict__ ei,
                           const float* __restrict__ ew) {
    int e = blockIdx.x * blockDim.x + threadIdx.x;
    if (e < N_EDGES) {
        int c = eidx(ei, 1, e);
        unsigned int wf = __float2uint_rn(ew[e] * 16777216.0f);   // 24.8-ish fixed
        unsigned long long v = (1ull << 40) | (unsigned long long)wf;
        atomicAdd(&g_degcnt[c], v);
    }
}

// ---------------- single-block scan: indptr/cursor/count/dinv ----------------
#define SCAN_T 1024
#define SCAN_CH 49                         // ceil(50000/1024)
__global__ __launch_bounds__(SCAN_T) void k_scan() {
    __shared__ int sh[SCAN_T];
    int tid = threadIdx.x;
    int base = tid * SCAN_CH;
    int local = 0;
    #pragma unroll 7
    for (int j = 0; j < SCAN_CH; j++) {
        int i = base + j;
        if (i < N_NODES) local += (int)(g_degcnt[i] >> 40);
    }
    sh[tid] = local;
    __syncthreads();
    #pragma unroll
    for (int off = 1; off < SCAN_T; off <<= 1) {
        int t = (tid >= off) ? sh[tid - off] : 0;
        __syncthreads();
        sh[tid] += t;
        __syncthreads();
    }
    int pref = sh[tid] - local;            // exclusive prefix for this chunk
    const float s24 = 1.0f / 16777216.0f;
    #pragma unroll 7
    for (int j = 0; j < SCAN_CH; j++) {
        int i = base + j;
        if (i < N_NODES) {
            unsigned long long v = g_degcnt[i];
            int c = (int)(v >> 40);
            g_indptr[i] = pref;
            g_cursor[i] = pref;
            g_count[i]  = c;
            pref += c;
            float deg = 1.0f + (float)(v & 0xFFFFFFFFFFull) * s24;
            g_dinv[i] = rsqrtf(deg);
        }
    }
}

__global__ void k_scatter(const void* __restrict__ ei,
                          const float* __restrict__ ew) {
    int e = blockIdx.x * blockDim.x + threadIdx.x;
    if (e < N_EDGES) {
        int r = eidx(ei, 0, e);
        int c = eidx(ei, 1, e);
        int pos = atomicAdd(&g_cursor[c], 1);
        g_esrc[pos] = r;
        g_enorm[pos] = g_dinv[r] * ew[e] * g_dinv[c];
    }
}

// ---------------- bf16 aggregation (warp per node, W words per lane, 4x unroll) ----
template <int W>
__global__ void k_agg_bf(const uint32_t* __restrict__ src, uint32_t* __restrict__ dst) {
    int gw = (blockIdx.x * blockDim.x + threadIdx.x) >> 5;
    int lane = threadIdx.x & 31;
    if (gw >= N_NODES) return;
    const int rs = W * 32;
    const uint32_t* sl = src + lane * W;
    float dn = g_dinv[gw], sw = dn * dn;
    uint32_t u[W];
    {
        const uint32_t* p = sl + (size_t)gw * rs;
        if (W == 4) *(uint4*)u = *(const uint4*)p; else *(uint2*)u = *(const uint2*)p;
    }
    float acc[2 * W];
    #pragma unroll
    for (int w = 0; w < W; w++) {
        acc[2 * w]     = sw * bflo(u[w]);
        acc[2 * w + 1] = sw * bfhi(u[w]);
    }
    int i = g_indptr[gw];
    int end = i + g_count[gw];
    for (; i + 4 <= end; i += 4) {
        int r0 = g_esrc[i],     r1 = g_esrc[i + 1];
        int r2 = g_esrc[i + 2], r3 = g_esrc[i + 3];
        float w0 = g_enorm[i],     w1 = g_enorm[i + 1];
        float w2 = g_enorm[i + 2], w3 = g_enorm[i + 3];
        uint32_t u0[W], u1[W], u2[W], u3[W];
        if (W == 4) {
            *(uint4*)u0 = *(const uint4*)(sl + (size_t)r0 * rs);
            *(uint4*)u1 = *(const uint4*)(sl + (size_t)r1 * rs);
            *(uint4*)u2 = *(const uint4*)(sl + (size_t)r2 * rs);
            *(uint4*)u3 = *(const uint4*)(sl + (size_t)r3 * rs);
        } else {
            *(uint2*)u0 = *(const uint2*)(sl + (size_t)r0 * rs);
            *(uint2*)u1 = *(const uint2*)(sl + (size_t)r1 * rs);
            *(uint2*)u2 = *(const uint2*)(sl + (size_t)r2 * rs);
            *(uint2*)u3 = *(const uint2*)(sl + (size_t)r3 * rs);
        }
        #pragma unroll
        for (int w = 0; w < W; w++) {
            acc[2 * w]     += w0 * bflo(u0[w]) + w1 * bflo(u1[w])
                            + w2 * bflo(u2[w]) + w3 * bflo(u3[w]);
            acc[2 * w + 1] += w0 * bfhi(u0[w]) + w1 * bfhi(u1[w])
                            + w2 * bfhi(u2[w]) + w3 * bfhi(u3[w]);
        }
    }
    for (; i < end; i++) {
        int r0 = g_esrc[i];
        float w0 = g_enorm[i];
        uint32_t u0[W];
        if (W == 4) *(uint4*)u0 = *(const uint4*)(sl + (size_t)r0 * rs);
        else        *(uint2*)u0 = *(const uint2*)(sl + (size_t)r0 * rs);
        #pragma unroll
        for (int w = 0; w < W; w++) {
            acc[2 * w]     += w0 * bflo(u0[w]);
            acc[2 * w + 1] += w0 * bfhi(u0[w]);
        }
    }
    uint32_t o[W];
    #pragma unroll
    for (int w = 0; w < W; w++) o[w] = bfpack(acc[2 * w], acc[2 * w + 1]);
    uint32_t* q = dst + (size_t)gw * rs + lane * W;
    if (W == 4) *(uint4*)q = *(const uint4*)o; else *(uint2*)q = *(const uint2*)o;
}

// ---------------- fused final: fp16 agg (dim 128) + bias + log_softmax ----------------
__global__ void k_agg_softmax(const uint32_t* __restrict__ src,
                              const float* __restrict__ bl,
                              float* __restrict__ out) {
    int gw = (blockIdx.x * blockDim.x + threadIdx.x) >> 5;
    int lane = threadIdx.x & 31;
    if (gw >= N_NODES) return;
    const int rs = 64;
    const uint32_t* sl = src + lane * 2;
    float dn = g_dinv[gw], sw = dn * dn;
    float acc[4];
    {
        uint2 u = *(const uint2*)(sl + (size_t)gw * rs);
        float2 a = __half22float2(*(__half2*)&u.x);
        float2 b = __half22float2(*(__half2*)&u.y);
        acc[0] = sw * a.x; acc[1] = sw * a.y; acc[2] = sw * b.x; acc[3] = sw * b.y;
    }
    int i = g_indptr[gw];
    int end = i + g_count[gw];
    for (; i + 4 <= end; i += 4) {
        int r0 = g_esrc[i],     r1 = g_esrc[i + 1];
        int r2 = g_esrc[i + 2], r3 = g_esrc[i + 3];
        float w0 = g_enorm[i],     w1 = g_enorm[i + 1];
        float w2 = g_enorm[i + 2], w3 = g_enorm[i + 3];
        uint2 u0 = *(const uint2*)(sl + (size_t)r0 * rs);
        uint2 u1 = *(const uint2*)(sl + (size_t)r1 * rs);
        uint2 u2 = *(const uint2*)(sl + (size_t)r2 * rs);
        uint2 u3 = *(const uint2*)(sl + (size_t)r3 * rs);
        float2 a0 = __half22float2(*(__half2*)&u0.x), b0 = __half22float2(*(__half2*)&u0.y);
        float2 a1 = __half22float2(*(__half2*)&u1.x), b1 = __half22float2(*(__half2*)&u1.y);
        float2 a2 = __half22float2(*(__half2*)&u2.x), b2 = __half22float2(*(__half2*)&u2.y);
        float2 a3 = __half22float2(*(__half2*)&u3.x), b3 = __half22float2(*(__half2*)&u3.y);
        acc[0] += w0 * a0.x + w1 * a1.x + w2 * a2.x + w3 * a3.x;
        acc[1] += w0 * a0.y + w1 * a1.y + w2 * a2.y + w3 * a3.y;
        acc[2] += w0 * b0.x + w1 * b1.x + w2 * b2.x + w3 * b3.x;
        acc[3] += w0 * b0.y + w1 * b1.y + w2 * b2.y + w3 * b3.y;
    }
    for (; i < end; i++) {
        int r0 = g_esrc[i];
        float w0 = g_enorm[i];
        uint2 u0 = *(const uint2*)(sl + (size_t)r0 * rs);
        float2 a0 = __half22float2(*(__half2*)&u0.x);
        float2 b0 = __half22float2(*(__half2*)&u0.y);
        acc[0] += w0 * a0.x; acc[1] += w0 * a0.y;
        acc[2] += w0 * b0.x; acc[3] += w0 * b0.y;
    }
    float4 b = ((const float4*)bl)[lane];
    acc[0] += b.x; acc[1] += b.y; acc[2] += b.z; acc[3] += b.w;
    float m = fmaxf(fmaxf(acc[0], acc[1]), fmaxf(acc[2], acc[3]));
    #pragma unroll
    for (int o = 16; o; o >>= 1) m = fmaxf(m, __shfl_xor_sync(0xFFFFFFFFu, m, o));
    float s = expf(acc[0] - m) + expf(acc[1] - m) + expf(acc[2] - m) + expf(acc[3] - m);
    #pragma unroll
    for (int o = 16; o; o >>= 1) s += __shfl_xor_sync(0xFFFFFFFFu, s, o);
    float lse = m + logf(s);
    float4 o4 = make_float4(acc[0] - lse, acc[1] - lse, acc[2] - lse, acc[3] - lse);
    ((float4*)out)[gw * 32 + lane] = o4;
}

// ---------------- fused weight transposes: Wt[NC][K] = bf16(W[K][NC]) ----------------
__global__ void k_transpose_all(const float* __restrict__ W0,
                                const float* __restrict__ W1,
                                const float* __restrict__ Wl) {
    __shared__ float t[32][33];
    int bid = blockIdx.x;
    const float* W; uint16_t* D; int K, NC, tk, tn;
    if (bid < 32)      { W = W0; D = g_wt0; K = DIM_IN;  NC = DIM_HID; int b = bid;      tk = b & 3; tn = b >> 2; }
    else if (bid < 96) { W = W1; D = g_wt1; K = DIM_HID; NC = DIM_HID; int b = bid - 32; tk = b & 7; tn = b >> 3; }
    else               { W = Wl; D = g_wt2; K = DIM_HID; NC = DIM_OUT; int b = bid - 96; tk = b & 7; tn = b >> 3; }
    int bx = tk * 32, by = tn * 32;
    int x = threadIdx.x, y = threadIdx.y;
    for (int i = y; i < 32; i += 8)
        t[i][x] = W[(size_t)(bx + i) * NC + by + x];
    __syncthreads();
    for (int i = y; i < 32; i += 8)
        D[(size_t)(by + i) * K + bx + x] = bf1(t[x][i]);
}

// ---------------- bf16 mma.sync GEMM, BM=128 BN=128 BK=64, cp.async 2-stage ----
// 8 warps (4m x 2n), warp tile 32x64. OUT: 0 = fp32, 1 = bf16, 2 = fp16
#define SPAD 36
#define TILEW (128 * SPAD)                 // words per matrix tile buffer
#define GEMM_SMEM (4 * TILEW * 4)          // 73728 bytes
template <int K_, int MODE, int OUT>
__global__ __launch_bounds__(256) void k_gemm_bf(
    const uint32_t* __restrict__ A, const uint16_t* __restrict__ Bw16,
    void* __restrict__ C, int M, int NC,
    const float* __restrict__ bias, const float* __restrict__ bng,
    const float* __restrict__ bnb) {
    extern __shared__ uint32_t dsm[];
    const int tid = threadIdx.x;
    const int wid = tid >> 5;
    const int lane = tid & 31;
    const int gid = lane >> 2;
    const int tig = lane & 3;
    const int warp_m = wid & 3;
    const int warp_n = wid >> 2;
    const int m0 = blockIdx.x * 128;
    const int n0 = blockIdx.y * 128;
    const int KW = K_ >> 1;
    const uint32_t* Bw = (const uint32_t*)Bw16;
    const int NIT = KW / 32;

    float acc[2][8][4];
    #pragma unroll
    for (int mi = 0; mi < 2; mi++)
        #pragma unroll
        for (int ni = 0; ni < 8; ni++)
            #pragma unroll
            for (int j = 0; j < 4; j++) acc[mi][ni][j] = 0.f;

    // stage loader: buffer s (0/1), k-offset kt (words)
    auto load_tile = [&](int s, int kt) {
        uint32_t abase = smem_u32(dsm + s * 2 * TILEW);
        uint32_t bbase = smem_u32(dsm + s * 2 * TILEW + TILEW);
        #pragma unroll
        for (int l = 0; l < 4; l++) {
            int t = tid + l * 256;
            int r = t >> 3, q = t & 7;
            int gm = m0 + r;
            const uint32_t* gp = (gm < M) ? &A[(size_t)gm * KW + kt + q * 4] : A;
            cpa16(abase + (r * SPAD + q * 4) * 4, gp, (gm < M) ? 16 : 0);
        }
        #pragma unroll
        for (int l = 0; l < 4; l++) {
            int t = tid + l * 256;
            int r = t >> 3, q = t & 7;
            cpa16(bbase + (r * SPAD + q * 4) * 4,
                  &Bw[(size_t)(n0 + r) * KW + kt + q * 4], 16);
        }
        CP_COMMIT();
    };

    load_tile(0, 0);
    #pragma unroll 1
    for (int it = 0; it < NIT; it++) {
        if (it + 1 < NIT) {
            load_tile((it + 1) & 1, (it + 1) * 32);
            CP_WAIT(1);
        } else {
            CP_WAIT(0);
        }
        __syncthreads();
        const uint32_t* As = dsm + (it & 1) * 2 * TILEW;
        const uint32_t* Bs = As + TILEW;
        #pragma unroll
        for (int g8 = 0; g8 < 32; g8 += 8) {
            uint32_t a[2][4], b[8][2];
            #pragma unroll
            for (int mi = 0; mi < 2; mi++) {
                int mlo = warp_m * 32 + mi * 16 + gid;
                a[mi][0] = As[mlo * SPAD + g8 + tig];
                a[mi][1] = As[(mlo + 8) * SPAD + g8 + tig];
                a[mi][2] = As[mlo * SPAD + g8 + tig + 4];
                a[mi][3] = As[(mlo + 8) * SPAD + g8 + tig + 4];
            }
            #pragma unroll
            for (int ni = 0; ni < 8; ni++) {
                int n = warp_n * 64 + ni * 8 + gid;
                b[ni][0] = Bs[n * SPAD + g8 + tig];
                b[ni][1] = Bs[n * SPAD + g8 + tig + 4];
            }
            #pragma unroll
            for (int mi = 0; mi < 2; mi++)
                #pragma unroll
                for (int ni = 0; ni < 8; ni++)
                    mma_bf16(acc[mi][ni], a[mi], b[ni]);
        }
        __syncthreads();
    }

    const float inv = rsqrtf(1.0f + 1e-5f);
    #pragma unroll
    for (int ni = 0; ni < 8; ni++) {
        int gn = n0 + warp_n * 64 + ni * 8 + tig * 2;
        float bi0 = 0.f, bi1 = 0.f, sc0 = 0.f, sc1 = 0.f, bb0 = 0.f, bb1 = 0.f;
        if (MODE == 1) {
            bi0 = __ldg(&bias[gn]);      bi1 = __ldg(&bias[gn + 1]);
            sc0 = __ldg(&bng[gn]) * inv; sc1 = __ldg(&bng[gn + 1]) * inv;
            bb0 = __ldg(&bnb[gn]);       bb1 = __ldg(&bnb[gn + 1]);
        }
        #pragma unroll
        for (int mi = 0; mi < 2; mi++) {
            int r0 = m0 + warp_m * 32 + mi * 16 + gid;
            #pragma unroll
            for (int h = 0; h < 2; h++) {
                int gm = r0 + h * 8;
                if (gm < M) {
                    float v0 = acc[mi][ni][h * 2 + 0];
                    float v1 = acc[mi][ni][h * 2 + 1];
                    if (MODE == 1) {
                        v0 = fmaxf(fmaf(v0 + bi0, sc0, bb0), 0.f);
                        v1 = fmaxf(fmaf(v1 + bi1, sc1, bb1), 0.f);
                    }
                    if (OUT == 1) {
                        ((uint32_t*)C)[(size_t)gm * (NC >> 1) + (gn >> 1)] = bfpack(v0, v1);
                    } else if (OUT == 2) {
                        ((uint32_t*)C)[(size_t)gm * (NC >> 1) + (gn >> 1)] = hfpack(v0, v1);
                    } else {
                        *(float2*)&((float*)C)[(size_t)gm * NC + gn] = make_float2(v0, v1);
                    }
                }
            }
        }
    }
}

// ---------------- driver ----------------
extern "C" void kernel_launch(void* const* d_in, const int* in_sizes, int n_in,
                              void* d_out, int out_size) {
    const float* x   = (const float*)d_in[0];
    const void*  ei  = d_in[1];
    const float* ew  = (const float*)d_in[2];
    const float* W0  = (const float*)d_in[3];
    const float* b0  = (const float*)d_in[4];
    const float* W1  = (const float*)d_in[5];
    const float* b1  = (const float*)d_in[6];
    const float* Wl  = (const float*)d_in[7];
    const float* bl  = (const float*)d_in[8];
    const float* g0  = (const float*)d_in[9];
    const float* be0 = (const float*)d_in[10];
    const float* g1  = (const float*)d_in[11];
    const float* be1 = (const float*)d_in[12];
    float* out = (float*)d_out;

    float *bufA = nullptr, *bufB = nullptr;
    uint16_t *wt0 = nullptr, *wt1 = nullptr, *wt2 = nullptr;
    cudaGetSymbolAddress((void**)&bufA, g_bufA);
    cudaGetSymbolAddress((void**)&bufB, g_bufB);
    cudaGetSymbolAddress((void**)&wt0, g_wt0);
    cudaGetSymbolAddress((void**)&wt1, g_wt1);
    cudaGetSymbolAddress((void**)&wt2, g_wt2);
    uint32_t* wA = (uint32_t*)bufA;
    uint32_t* wB = (uint32_t*)bufB;

    cudaFuncSetAttribute(k_gemm_bf<128, 1, 1>, cudaFuncAttributeMaxDynamicSharedMemorySize, GEMM_SMEM);
    cudaFuncSetAttribute(k_gemm_bf<256, 1, 1>, cudaFuncAttributeMaxDynamicSharedMemorySize, GEMM_SMEM);
    cudaFuncSetAttribute(k_gemm_bf<256, 0, 2>, cudaFuncAttributeMaxDynamicSharedMemorySize, GEMM_SMEM);

    const int NB_E = (N_EDGES + 255) / 256;
    const int NB_W = (N_NODES * 32 + 255) / 256;
    const int MT   = (N_NODES + 127) / 128;

    // fused pre (detect + init + x->bf16 into wB) and weight transposes
    k_pre<<<NB_INIT + NB_CVT, 256>>>((const int*)ei, x, wB);
    k_transpose_all<<<128, dim3(32, 8)>>>(W0, W1, Wl);

    // graph build
    k_degcount<<<NB_E, 256>>>(ei, ew);
    k_scan<<<1, SCAN_T>>>();
    k_scatter<<<NB_E, 256>>>(ei, ew);

    // layer 0: agg_bf(x_bf)[N,128] wB -> wA; bf16 GEMM 128->256 -> wB
    k_agg_bf<2><<<NB_W, 256>>>(wB, wA);
    k_gemm_bf<128, 1, 1><<<dim3(MT, DIM_HID / 128), 256, GEMM_SMEM>>>(
        wA, wt0, wB, N_NODES, DIM_HID, b0, g0, be0);

    // layer 1: agg_bf[N,256] wB -> wA; bf16 GEMM 256->256 -> wB
    k_agg_bf<4><<<NB_W, 256>>>(wB, wA);
    k_gemm_bf<256, 1, 1><<<dim3(MT, DIM_HID / 128), 256, GEMM_SMEM>>>(
        wA, wt1, wB, N_NODES, DIM_HID, b1, g1, be1);

    // layer 2: bf16 GEMM 256->128 (plain, fp16 out) wB -> wA; fused agg+softmax
    k_gemm_bf<256, 0, 2><<<dim3(MT, DIM_OUT / 128), 256, GEMM_SMEM>>>(
        wB, wt2, wA, N_NODES, DIM_OUT, nullptr, nullptr, nullptr);
    k_agg_softmax<<<NB_W, 256>>>(wA, bl, out);
}

// round 16
// speedup vs baseline: 1.6315x; 1.6315x over previous
#include <cuda_runtime.h>
#include <cuda_fp16.h>
#include <cstdint>

#define N_NODES 50000
#define N_EDGES 800000
#define DIM_IN  128
#define DIM_HID 256
#define DIM_OUT 128
#define SCAN_B  512
#define SCAN_NB 98   // ceil(50000/512)

// ---------------- scratch (no allocations allowed) ----------------
__device__ __align__(16) float g_bufA[N_NODES * DIM_HID];   // 51.2 MB
__device__ __align__(16) float g_bufB[N_NODES * DIM_HID];   // 51.2 MB
__device__ __align__(16) uint16_t g_wt0[DIM_IN  * DIM_HID];
__device__ __align__(16) uint16_t g_wt1[DIM_HID * DIM_HID];
__device__ __align__(16) uint16_t g_wt2[DIM_HID * DIM_OUT];
__device__ unsigned long long g_degcnt[N_NODES];   // count<<40 | deg_fixed(2^-24)
__device__ float g_dinv[N_NODES];
__device__ int   g_count[N_NODES];
__device__ int   g_indptr[N_NODES];
__device__ int   g_cursor[N_NODES];
__device__ int   g_blocksums[SCAN_NB];
__device__ int   g_esrc[N_EDGES];
__device__ float g_enorm[N_EDGES];
__device__ int   g_i64;

__device__ __forceinline__ int clampi(int v) {
    return min(max(v, 0), N_NODES - 1);
}
__device__ __forceinline__ int eidx(const void* ei, int j, int e) {
    if (g_i64) return clampi((int)((const long long*)ei)[j * N_EDGES + e]);
    return clampi(((const int*)ei)[j * N_EDGES + e]);
}

// bf16 helpers
__device__ __forceinline__ float bflo(uint32_t u) { return __uint_as_float(u << 16); }
__device__ __forceinline__ float bfhi(uint32_t u) { return __uint_as_float(u & 0xffff0000u); }
__device__ __forceinline__ uint32_t bfpack(float lo, float hi) {
    uint32_t r;
    asm("cvt.rn.bf16x2.f32 %0, %1, %2;" : "=r"(r) : "f"(hi), "f"(lo));
    return r;
}
__device__ __forceinline__ uint16_t bf1(float f) {
    uint16_t r;
    asm("cvt.rn.bf16.f32 %0, %1;" : "=h"(r) : "f"(f));
    return r;
}
__device__ __forceinline__ uint32_t hfpack(float lo, float hi) {
    uint32_t r;
    asm("cvt.rn.f16x2.f32 %0, %1, %2;" : "=r"(r) : "f"(hi), "f"(lo));
    return r;
}
__device__ __forceinline__ void mma_bf16(float* c, const uint32_t* a, const uint32_t* b) {
    asm volatile(
        "mma.sync.aligned.m16n8k16.row.col.f32.bf16.bf16.f32 "
        "{%0,%1,%2,%3}, {%4,%5,%6,%7}, {%8,%9}, {%0,%1,%2,%3};"
        : "+f"(c[0]), "+f"(c[1]), "+f"(c[2]), "+f"(c[3])
        : "r"(a[0]), "r"(a[1]), "r"(a[2]), "r"(a[3]), "r"(b[0]), "r"(b[1]));
}
// cp.async helpers (sm_80 baseline PTX)
__device__ __forceinline__ uint32_t smem_u32(const void* p) {
    uint32_t a;
    asm("{ .reg .u64 t; cvta.to.shared.u64 t, %1; cvt.u32.u64 %0, t; }"
        : "=r"(a) : "l"(p));
    return a;
}
__device__ __forceinline__ void cpa16(uint32_t saddr, const void* g, int srcbytes) {
    asm volatile("cp.async.cg.shared.global [%0], [%1], 16, %2;"
                 :: "r"(saddr), "l"(g), "r"(srcbytes));
}
#define CP_COMMIT() asm volatile("cp.async.commit_group;" ::: "memory")
#define CP_WAIT(N)  asm volatile("cp.async.wait_group %0;" :: "n"(N) : "memory")

// ---------------- fused: dtype detect (block 0) + init + x->bf16 ----------------
#define NB_INIT 196                       // ceil(50000/256)
#define NB_CVT  12500                     // 50000*64/256 words
__global__ void k_pre(const int* __restrict__ ei32,
                      const float* __restrict__ x, uint32_t* __restrict__ xb) {
    int bid = blockIdx.x;
    if (bid == 0) {
        __shared__ int s_nz;
        if (threadIdx.x == 0) s_nz = 0;
        __syncthreads();
        int nz = 0;
        for (int t = threadIdx.x; t < 2048; t += blockDim.x)
            if (ei32[2 * t + 1] != 0) nz = 1;
        if (nz) atomicOr(&s_nz, 1);
        __syncthreads();
        if (threadIdx.x == 0) g_i64 = (s_nz == 0) ? 1 : 0;
    }
    if (bid < NB_INIT) {
        int i = bid * 256 + threadIdx.x;
        if (i < N_NODES) g_degcnt[i] = 0ull;
    } else {
        int i = (bid - NB_INIT) * 256 + threadIdx.x;
        if (i < N_NODES * (DIM_IN / 2)) {
            float2 v = ((const float2*)x)[i];
            xb[i] = bfpack(v.x, v.y);
        }
    }
}

// ---------------- graph build: packed degree+count, single atomic/edge ----------
__global__ void k_degcount(const void* __restrict__ ei,
                           const float* __restrict__ ew) {
    int e = blockIdx.x * blockDim.x + threadIdx.x;
    if (e < N_EDGES) {
        int c = eidx(ei, 1, e);
        unsigned int wf = __float2uint_rn(ew[e] * 16777216.0f);   // fixed point 2^-24
        unsigned long long v = (1ull << 40) | (unsigned long long)wf;
        atomicAdd(&g_degcnt[c], v);
    }
}

// ---------------- 3-phase chip-wide scan ----------------
__global__ void k_scan1() {
    __shared__ int sh[SCAN_B];
    int tid = threadIdx.x;
    int i = blockIdx.x * SCAN_B + tid;
    int v = (i < N_NODES) ? (int)(g_degcnt[i] >> 40) : 0;
    sh[tid] = v;
    __syncthreads();
    #pragma unroll
    for (int off = 1; off < SCAN_B; off <<= 1) {
        int t = (tid >= off) ? sh[tid - off] : 0;
        __syncthreads();
        sh[tid] += t;
        __syncthreads();
    }
    if (i < N_NODES) g_indptr[i] = sh[tid] - v;   // exclusive (within block)
    if (tid == SCAN_B - 1) g_blocksums[blockIdx.x] = sh[SCAN_B - 1];
}

__global__ void k_scan2() {
    if (threadIdx.x == 0) {
        int s = 0;
        for (int b = 0; b < SCAN_NB; b++) {
            int t = g_blocksums[b];
            g_blocksums[b] = s;
            s += t;
        }
    }
}

__global__ void k_scan3() {      // apply block offsets + count/cursor/dinv
    int i = blockIdx.x * blockDim.x + threadIdx.x;
    if (i < N_NODES) {
        unsigned long long v = g_degcnt[i];
        int p = g_indptr[i] + g_blocksums[i >> 9];
        g_indptr[i] = p;
        g_cursor[i] = p;
        g_count[i]  = (int)(v >> 40);
        float deg = 1.0f + (float)(v & 0xFFFFFFFFFFull) * (1.0f / 16777216.0f);
        g_dinv[i] = rsqrtf(deg);
    }
}

__global__ void k_scatter(const void* __restrict__ ei,
                          const float* __restrict__ ew) {
    int e = blockIdx.x * blockDim.x + threadIdx.x;
    if (e < N_EDGES) {
        int r = eidx(ei, 0, e);
        int c = eidx(ei, 1, e);
        int pos = atomicAdd(&g_cursor[c], 1);
        g_esrc[pos] = r;
        g_enorm[pos] = g_dinv[r] * ew[e] * g_dinv[c];
    }
}

// ---------------- bf16 aggregation (warp per node, W words per lane, 4x unroll) ----
template <int W>
__global__ void k_agg_bf(const uint32_t* __restrict__ src, uint32_t* __restrict__ dst) {
    int gw = (blockIdx.x * blockDim.x + threadIdx.x) >> 5;
    int lane = threadIdx.x & 31;
    if (gw >= N_NODES) return;
    const int rs = W * 32;
    const uint32_t* sl = src + lane * W;
    float dn = g_dinv[gw], sw = dn * dn;
    uint32_t u[W];
    {
        const uint32_t* p = sl + (size_t)gw * rs;
        if (W == 4) *(uint4*)u = *(const uint4*)p; else *(uint2*)u = *(const uint2*)p;
    }
    float acc[2 * W];
    #pragma unroll
    for (int w = 0; w < W; w++) {
        acc[2 * w]     = sw * bflo(u[w]);
        acc[2 * w + 1] = sw * bfhi(u[w]);
    }
    int i = g_indptr[gw];
    int end = i + g_count[gw];
    for (; i + 4 <= end; i += 4) {
        int r0 = g_esrc[i],     r1 = g_esrc[i + 1];
        int r2 = g_esrc[i + 2], r3 = g_esrc[i + 3];
        float w0 = g_enorm[i],     w1 = g_enorm[i + 1];
        float w2 = g_enorm[i + 2], w3 = g_enorm[i + 3];
        uint32_t u0[W], u1[W], u2[W], u3[W];
        if (W == 4) {
            *(uint4*)u0 = *(const uint4*)(sl + (size_t)r0 * rs);
            *(uint4*)u1 = *(const uint4*)(sl + (size_t)r1 * rs);
            *(uint4*)u2 = *(const uint4*)(sl + (size_t)r2 * rs);
            *(uint4*)u3 = *(const uint4*)(sl + (size_t)r3 * rs);
        } else {
            *(uint2*)u0 = *(const uint2*)(sl + (size_t)r0 * rs);
            *(uint2*)u1 = *(const uint2*)(sl + (size_t)r1 * rs);
            *(uint2*)u2 = *(const uint2*)(sl + (size_t)r2 * rs);
            *(uint2*)u3 = *(const uint2*)(sl + (size_t)r3 * rs);
        }
        #pragma unroll
        for (int w = 0; w < W; w++) {
            acc[2 * w]     += w0 * bflo(u0[w]) + w1 * bflo(u1[w])
                            + w2 * bflo(u2[w]) + w3 * bflo(u3[w]);
            acc[2 * w + 1] += w0 * bfhi(u0[w]) + w1 * bfhi(u1[w])
                            + w2 * bfhi(u2[w]) + w3 * bfhi(u3[w]);
        }
    }
    for (; i < end; i++) {
        int r0 = g_esrc[i];
        float w0 = g_enorm[i];
        uint32_t u0[W];
        if (W == 4) *(uint4*)u0 = *(const uint4*)(sl + (size_t)r0 * rs);
        else        *(uint2*)u0 = *(const uint2*)(sl + (size_t)r0 * rs);
        #pragma unroll
        for (int w = 0; w < W; w++) {
            acc[2 * w]     += w0 * bflo(u0[w]);
            acc[2 * w + 1] += w0 * bfhi(u0[w]);
        }
    }
    uint32_t o[W];
    #pragma unroll
    for (int w = 0; w < W; w++) o[w] = bfpack(acc[2 * w], acc[2 * w + 1]);
    uint32_t* q = dst + (size_t)gw * rs + lane * W;
    if (W == 4) *(uint4*)q = *(const uint4*)o; else *(uint2*)q = *(const uint2*)o;
}

// ---------------- fused final: fp16 agg (dim 128) + bias + log_softmax ----------------
__global__ void k_agg_softmax(const uint32_t* __restrict__ src,
                              const float* __restrict__ bl,
                              float* __restrict__ out) {
    int gw = (blockIdx.x * blockDim.x + threadIdx.x) >> 5;
    int lane = threadIdx.x & 31;
    if (gw >= N_NODES) return;
    const int rs = 64;
    const uint32_t* sl = src + lane * 2;
    float dn = g_dinv[gw], sw = dn * dn;
    float acc[4];
    {
        uint2 u = *(const uint2*)(sl + (size_t)gw * rs);
        float2 a = __half22float2(*(__half2*)&u.x);
        float2 b = __half22float2(*(__half2*)&u.y);
        acc[0] = sw * a.x; acc[1] = sw * a.y; acc[2] = sw * b.x; acc[3] = sw * b.y;
    }
    int i = g_indptr[gw];
    int end = i + g_count[gw];
    for (; i + 4 <= end; i += 4) {
        int r0 = g_esrc[i],     r1 = g_esrc[i + 1];
        int r2 = g_esrc[i + 2], r3 = g_esrc[i + 3];
        float w0 = g_enorm[i],     w1 = g_enorm[i + 1];
        float w2 = g_enorm[i + 2], w3 = g_enorm[i + 3];
        uint2 u0 = *(const uint2*)(sl + (size_t)r0 * rs);
        uint2 u1 = *(const uint2*)(sl + (size_t)r1 * rs);
        uint2 u2 = *(const uint2*)(sl + (size_t)r2 * rs);
        uint2 u3 = *(const uint2*)(sl + (size_t)r3 * rs);
        float2 a0 = __half22float2(*(__half2*)&u0.x), b0 = __half22float2(*(__half2*)&u0.y);
        float2 a1 = __half22float2(*(__half2*)&u1.x), b1 = __half22float2(*(__half2*)&u1.y);
        float2 a2 = __half22float2(*(__half2*)&u2.x), b2 = __half22float2(*(__half2*)&u2.y);
        float2 a3 = __half22float2(*(__half2*)&u3.x), b3 = __half22float2(*(__half2*)&u3.y);
        acc[0] += w0 * a0.x + w1 * a1.x + w2 * a2.x + w3 * a3.x;
        acc[1] += w0 * a0.y + w1 * a1.y + w2 * a2.y + w3 * a3.y;
        acc[2] += w0 * b0.x + w1 * b1.x + w2 * b2.x + w3 * b3.x;
        acc[3] += w0 * b0.y + w1 * b1.y + w2 * b2.y + w3 * b3.y;
    }
    for (; i < end; i++) {
        int r0 = g_esrc[i];
        float w0 = g_enorm[i];
        uint2 u0 = *(const uint2*)(sl + (size_t)r0 * rs);
        float2 a0 = __half22float2(*(__half2*)&u0.x);
        float2 b0 = __half22float2(*(__half2*)&u0.y);
        acc[0] += w0 * a0.x; acc[1] += w0 * a0.y;
        acc[2] += w0 * b0.x; acc[3] += w0 * b0.y;
    }
    float4 b = ((const float4*)bl)[lane];
    acc[0] += b.x; acc[1] += b.y; acc[2] += b.z; acc[3] += b.w;
    float m = fmaxf(fmaxf(acc[0], acc[1]), fmaxf(acc[2], acc[3]));
    #pragma unroll
    for (int o = 16; o; o >>= 1) m = fmaxf(m, __shfl_xor_sync(0xFFFFFFFFu, m, o));
    float s = expf(acc[0] - m) + expf(acc[1] - m) + expf(acc[2] - m) + expf(acc[3] - m);
    #pragma unroll
    for (int o = 16; o; o >>= 1) s += __shfl_xor_sync(0xFFFFFFFFu, s, o);
    float lse = m + logf(s);
    float4 o4 = make_float4(acc[0] - lse, acc[1] - lse, acc[2] - lse, acc[3] - lse);
    ((float4*)out)[gw * 32 + lane] = o4;
}

// ---------------- fused weight transposes: Wt[NC][K] = bf16(W[K][NC]) ----------------
__global__ void k_transpose_all(const float* __restrict__ W0,
                                const float* __restrict__ W1,
                                const float* __restrict__ Wl) {
    __shared__ float t[32][33];
    int bid = blockIdx.x;
    const float* W; uint16_t* D; int K, NC, tk, tn;
    if (bid < 32)      { W = W0; D = g_wt0; K = DIM_IN;  NC = DIM_HID; int b = bid;      tk = b & 3; tn = b >> 2; }
    else if (bid < 96) { W = W1; D = g_wt1; K = DIM_HID; NC = DIM_HID; int b = bid - 32; tk = b & 7; tn = b >> 3; }
    else               { W = Wl; D = g_wt2; K = DIM_HID; NC = DIM_OUT; int b = bid - 96; tk = b & 7; tn = b >> 3; }
    int bx = tk * 32, by = tn * 32;
    int x = threadIdx.x, y = threadIdx.y;
    for (int i = y; i < 32; i += 8)
        t[i][x] = W[(size_t)(bx + i) * NC + by + x];
    __syncthreads();
    for (int i = y; i < 32; i += 8)
        D[(size_t)(by + i) * K + bx + x] = bf1(t[x][i]);
}

// ---------------- bf16 mma.sync GEMM, BM=128 BN=128 BK=64, cp.async 2-stage ----
// 8 warps (4m x 2n), warp tile 32x64. OUT: 0 = fp32, 1 = bf16, 2 = fp16
#define SPAD 36
#define TILEW (128 * SPAD)                 // words per matrix tile buffer
#define GEMM_SMEM (4 * TILEW * 4)          // 73728 bytes
template <int K_, int MODE, int OUT>
__global__ __launch_bounds__(256) void k_gemm_bf(
    const uint32_t* __restrict__ A, const uint16_t* __restrict__ Bw16,
    void* __restrict__ C, int M, int NC,
    const float* __restrict__ bias, const float* __restrict__ bng,
    const float* __restrict__ bnb) {
    extern __shared__ uint32_t dsm[];
    const int tid = threadIdx.x;
    const int wid = tid >> 5;
    const int lane = tid & 31;
    const int gid = lane >> 2;
    const int tig = lane & 3;
    const int warp_m = wid & 3;
    const int warp_n = wid >> 2;
    const int m0 = blockIdx.x * 128;
    const int n0 = blockIdx.y * 128;
    const int KW = K_ >> 1;
    const uint32_t* Bw = (const uint32_t*)Bw16;
    const int NIT = KW / 32;

    float acc[2][8][4];
    #pragma unroll
    for (int mi = 0; mi < 2; mi++)
        #pragma unroll
        for (int ni = 0; ni < 8; ni++)
            #pragma unroll
            for (int j = 0; j < 4; j++) acc[mi][ni][j] = 0.f;

    auto load_tile = [&](int s, int kt) {
        uint32_t abase = smem_u32(dsm + s * 2 * TILEW);
        uint32_t bbase = smem_u32(dsm + s * 2 * TILEW + TILEW);
        #pragma unroll
        for (int l = 0; l < 4; l++) {
            int t = tid + l * 256;
            int r = t >> 3, q = t & 7;
            int gm = m0 + r;
            const uint32_t* gp = (gm < M) ? &A[(size_t)gm * KW + kt + q * 4] : A;
            cpa16(abase + (r * SPAD + q * 4) * 4, gp, (gm < M) ? 16 : 0);
        }
        #pragma unroll
        for (int l = 0; l < 4; l++) {
            int t = tid + l * 256;
            int r = t >> 3, q = t & 7;
            cpa16(bbase + (r * SPAD + q * 4) * 4,
                  &Bw[(size_t)(n0 + r) * KW + kt + q * 4], 16);
        }
        CP_COMMIT();
    };

    load_tile(0, 0);
    #pragma unroll 1
    for (int it = 0; it < NIT; it++) {
        if (it + 1 < NIT) {
            load_tile((it + 1) & 1, (it + 1) * 32);
            CP_WAIT(1);
        } else {
            CP_WAIT(0);
        }
        __syncthreads();
        const uint32_t* As = dsm + (it & 1) * 2 * TILEW;
        const uint32_t* Bs = As + TILEW;
        #pragma unroll
        for (int g8 = 0; g8 < 32; g8 += 8) {
            uint32_t a[2][4], b[8][2];
            #pragma unroll
            for (int mi = 0; mi < 2; mi++) {
                int mlo = warp_m * 32 + mi * 16 + gid;
                a[mi][0] = As[mlo * SPAD + g8 + tig];
                a[mi][1] = As[(mlo + 8) * SPAD + g8 + tig];
                a[mi][2] = As[mlo * SPAD + g8 + tig + 4];
                a[mi][3] = As[(mlo + 8) * SPAD + g8 + tig + 4];
            }
            #pragma unroll
            for (int ni = 0; ni < 8; ni++) {
                int n = warp_n * 64 + ni * 8 + gid;
                b[ni][0] = Bs[n * SPAD + g8 + tig];
                b[ni][1] = Bs[n * SPAD + g8 + tig + 4];
            }
            #pragma unroll
            for (int mi = 0; mi < 2; mi++)
                #pragma unroll
                for (int ni = 0; ni < 8; ni++)
                    mma_bf16(acc[mi][ni], a[mi], b[ni]);
        }
        __syncthreads();
    }

    const float inv = rsqrtf(1.0f + 1e-5f);
    #pragma unroll
    for (int ni = 0; ni < 8; ni++) {
        int gn = n0 + warp_n * 64 + ni * 8 + tig * 2;
        float bi0 = 0.f, bi1 = 0.f, sc0 = 0.f, sc1 = 0.f, bb0 = 0.f, bb1 = 0.f;
        if (MODE == 1) {
            bi0 = __ldg(&bias[gn]);      bi1 = __ldg(&bias[gn + 1]);
            sc0 = __ldg(&bng[gn]) * inv; sc1 = __ldg(&bng[gn + 1]) * inv;
            bb0 = __ldg(&bnb[gn]);       bb1 = __ldg(&bnb[gn + 1]);
        }
        #pragma unroll
        for (int mi = 0; mi < 2; mi++) {
            int r0 = m0 + warp_m * 32 + mi * 16 + gid;
            #pragma unroll
            for (int h = 0; h < 2; h++) {
                int gm = r0 + h * 8;
                if (gm < M) {
                    float v0 = acc[mi][ni][h * 2 + 0];
                    float v1 = acc[mi][ni][h * 2 + 1];
                    if (MODE == 1) {
                        v0 = fmaxf(fmaf(v0 + bi0, sc0, bb0), 0.f);
                        v1 = fmaxf(fmaf(v1 + bi1, sc1, bb1), 0.f);
                    }
                    if (OUT == 1) {
                        ((uint32_t*)C)[(size_t)gm * (NC >> 1) + (gn >> 1)] = bfpack(v0, v1);
                    } else if (OUT == 2) {
                        ((uint32_t*)C)[(size_t)gm * (NC >> 1) + (gn >> 1)] = hfpack(v0, v1);
                    } else {
                        *(float2*)&((float*)C)[(size_t)gm * NC + gn] = make_float2(v0, v1);
                    }
                }
            }
        }
    }
}

// ---------------- driver ----------------
extern "C" void kernel_launch(void* const* d_in, const int* in_sizes, int n_in,
                              void* d_out, int out_size) {
    const float* x   = (const float*)d_in[0];
    const void*  ei  = d_in[1];
    const float* ew  = (const float*)d_in[2];
    const float* W0  = (const float*)d_in[3];
    const float* b0  = (const float*)d_in[4];
    const float* W1  = (const float*)d_in[5];
    const float* b1  = (const float*)d_in[6];
    const float* Wl  = (const float*)d_in[7];
    const float* bl  = (const float*)d_in[8];
    const float* g0  = (const float*)d_in[9];
    const float* be0 = (const float*)d_in[10];
    const float* g1  = (const float*)d_in[11];
    const float* be1 = (const float*)d_in[12];
    float* out = (float*)d_out;

    float *bufA = nullptr, *bufB = nullptr;
    uint16_t *wt0 = nullptr, *wt1 = nullptr, *wt2 = nullptr;
    cudaGetSymbolAddress((void**)&bufA, g_bufA);
    cudaGetSymbolAddress((void**)&bufB, g_bufB);
    cudaGetSymbolAddress((void**)&wt0, g_wt0);
    cudaGetSymbolAddress((void**)&wt1, g_wt1);
    cudaGetSymbolAddress((void**)&wt2, g_wt2);
    uint32_t* wA = (uint32_t*)bufA;
    uint32_t* wB = (uint32_t*)bufB;

    cudaFuncSetAttribute(k_gemm_bf<128, 1, 1>, cudaFuncAttributeMaxDynamicSharedMemorySize, GEMM_SMEM);
    cudaFuncSetAttribute(k_gemm_bf<256, 1, 1>, cudaFuncAttributeMaxDynamicSharedMemorySize, GEMM_SMEM);
    cudaFuncSetAttribute(k_gemm_bf<256, 0, 2>, cudaFuncAttributeMaxDynamicSharedMemorySize, GEMM_SMEM);

    const int NB_E = (N_EDGES + 255) / 256;
    const int NB_W = (N_NODES * 32 + 255) / 256;
    const int MT   = (N_NODES + 127) / 128;

    // fused pre (detect + init + x->bf16 into wB) and weight transposes
    k_pre<<<NB_INIT + NB_CVT, 256>>>((const int*)ei, x, wB);
    k_transpose_all<<<128, dim3(32, 8)>>>(W0, W1, Wl);

    // graph build
    k_degcount<<<NB_E, 256>>>(ei, ew);
    k_scan1<<<SCAN_NB, SCAN_B>>>();
    k_scan2<<<1, 32>>>();
    k_scan3<<<NB_INIT, 256>>>();
    k_scatter<<<NB_E, 256>>>(ei, ew);

    // layer 0: agg_bf(x_bf)[N,128] wB -> wA; bf16 GEMM 128->256 -> wB
    k_agg_bf<2><<<NB_W, 256>>>(wB, wA);
    k_gemm_bf<128, 1, 1><<<dim3(MT, DIM_HID / 128), 256, GEMM_SMEM>>>(
        wA, wt0, wB, N_NODES, DIM_HID, b0, g0, be0);

    // layer 1: agg_bf[N,256] wB -> wA; bf16 GEMM 256->256 -> wB
    k_agg_bf<4><<<NB_W, 256>>>(wB, wA);
    k_gemm_bf<256, 1, 1><<<dim3(MT, DIM_HID / 128), 256, GEMM_SMEM>>>(
        wA, wt1, wB, N_NODES, DIM_HID, b1, g1, be1);

    // layer 2: bf16 GEMM 256->128 (plain, fp16 out) wB -> wA; fused agg+softmax
    k_gemm_bf<256, 0, 2><<<dim3(MT, DIM_OUT / 128), 256, GEMM_SMEM>>>(
        wB, wt2, wA, N_NODES, DIM_OUT, nullptr, nullptr, nullptr);
    k_agg_softmax<<<NB_W, 256>>>(wA, bl, out);
}